// round 4
// baseline (speedup 1.0000x reference)
#include <cuda_runtime.h>
#include <math.h>

// Problem constants
#define M_DIM 256
#define Q_DIM 64
#define N_DIM 65536
#define NB 32            // columns per CTA (== warp size; lane = column)
#define THREADS 512
#define NWARP 16
#define T_ITERS 16
#define PM_ITERS 200
#define LAMBDA_STAR 0.1f
#define LAMBDA_O 0.1f
#define DT_STRIDE 260    // 256 + 4 pad (bank-conflict relief, keeps 16B alignment)

// eta, thr, c_q, c_m
__device__ float g_consts[4];

// ---------------------------------------------------------------------------
// Prep: G = D^T D, power iteration for alpha = lambda_max(G), derive constants.
// Single block, 256 threads.
// ---------------------------------------------------------------------------
__global__ void prep_kernel(const float* __restrict__ D)
{
    extern __shared__ float sm[];
    float* sD   = sm;                 // [256][64]
    float* sG   = sD + 256 * 64;      // [64][64]
    float* sx   = sG + 64 * 64;       // [64]
    float* sy   = sx + 64;            // [64]
    float* sred = sy + 64;            // [2]

    const int t = threadIdx.x;

    for (int i = t; i < 256 * 64; i += blockDim.x) sD[i] = D[i];
    __syncthreads();

    // G = D^T D : each thread computes a 4x4 block (16x16 grid of blocks)
    {
        const int bi = t & 15, bj = t >> 4;
        const int i0 = bi * 4, j0 = bj * 4;
        float acc[4][4];
        #pragma unroll
        for (int a = 0; a < 4; a++)
            #pragma unroll
            for (int b = 0; b < 4; b++) acc[a][b] = 0.f;

        for (int k = 0; k < 256; k++) {
            const float4 av = *(const float4*)&sD[k * 64 + i0];
            const float4 bv = *(const float4*)&sD[k * 64 + j0];
            const float ai[4] = {av.x, av.y, av.z, av.w};
            const float bjv[4] = {bv.x, bv.y, bv.z, bv.w};
            #pragma unroll
            for (int a = 0; a < 4; a++)
                #pragma unroll
                for (int b = 0; b < 4; b++) acc[a][b] += ai[a] * bjv[b];
        }
        #pragma unroll
        for (int a = 0; a < 4; a++)
            #pragma unroll
            for (int b = 0; b < 4; b++) sG[(i0 + a) * 64 + (j0 + b)] = acc[a][b];
    }

    if (t < 64) sx[t] = 1.0f;
    __syncthreads();

    float alpha = 0.f;
    for (int it = 0; it < PM_ITERS; it++) {
        if (t < 64) {
            const float* g = &sG[t * 64];
            float y = 0.f;
            #pragma unroll 8
            for (int j = 0; j < 64; j++) y += g[j] * sx[j];
            sy[t] = y;
        }
        __syncthreads();

        float ss = 0.f;
        if (t < 64) { float y = sy[t]; ss = y * y; }
        #pragma unroll
        for (int off = 16; off > 0; off >>= 1)
            ss += __shfl_down_sync(0xffffffffu, ss, off);
        if (t < 64 && (t & 31) == 0) sred[t >> 5] = ss;
        __syncthreads();

        const float nm = sqrtf(sred[0] + sred[1]);
        if (t < 64) sx[t] = sy[t] / nm;
        alpha = nm;
        __syncthreads();
    }

    if (t == 0) {
        const float eta = 1.0f / alpha;
        g_consts[0] = eta;
        g_consts[1] = LAMBDA_O * eta;                       // threshold (m rows)
        g_consts[2] = 1.0f - eta * LAMBDA_STAR;             // c_q
        g_consts[3] = 1.0f - eta * (1.0f + LAMBDA_STAR);    // c_m
    }
}

// ---------------------------------------------------------------------------
// Main ISTA kernel. One CTA = 32 columns (lane = column), state in SMEM:
//   b = [b_q(64); b_m(256)], Z likewise, per iteration:
//     Znew = relu(b - t); d = Znew - Z; Z = Znew
//     w = D @ d_q                 (256 x 32)
//     b_m += c_m*d_m - eta*w;  s = w + d_m  (stored in place of d_m)
//     y = D^T @ s                 (64 x 32)
//     b_q += c_q*d_q - eta*y
//   (last iteration skips the b-update; it is dead in the reference scan)
// ---------------------------------------------------------------------------
__global__ void __launch_bounds__(THREADS)
ista_kernel(const float* __restrict__ X, const float* __restrict__ D,
            float* __restrict__ out)
{
    extern __shared__ float sm[];
    float* sDT = sm;                        // [64][DT_STRIDE]  D^T (padded)
    float* sbq = sDT + 64 * DT_STRIDE;      // [64][32]
    float* sZq = sbq + 64 * NB;             // [64][32]
    float* sdq = sZq + 64 * NB;             // [64][32]
    float* sbm = sdq + 64 * NB;             // [256][32]
    float* sZm = sbm + 256 * NB;            // [256][32]
    float* sdm = sZm + 256 * NB;            // [256][32]  (dv, then s = w+dv)

    const int tid  = threadIdx.x;
    const int lane = tid & 31;
    const int wid  = tid >> 5;
    const int col0 = blockIdx.x * NB;

    const float eta = g_consts[0];
    const float thr = g_consts[1];
    const float cq  = g_consts[2];
    const float cm  = g_consts[3];

    // Load D transposed: sDT[q][k] = D[k][q]
    for (int k = wid; k < 256; k += NWARP) {
        #pragma unroll
        for (int q = lane; q < 64; q += 32)
            sDT[q * DT_STRIDE + k] = D[k * 64 + q];
    }

    // Load X tile; init b_m = eta*x, Z = 0; stash x in sdm for the b_q GEMV
    for (int r = wid; r < 256; r += NWARP) {
        const float x = X[(size_t)r * N_DIM + col0 + lane];
        const int idx = r * NB + lane;
        sdm[idx] = x;
        sbm[idx] = eta * x;
        sZm[idx] = 0.f;
    }
    for (int r = wid; r < 64; r += NWARP) sZq[r * NB + lane] = 0.f;
    __syncthreads();

    // b_q = eta * D^T x   (4 rows per warp)
    {
        const int r0 = wid * 4;
        float acc[4] = {0.f, 0.f, 0.f, 0.f};
        for (int k = 0; k < 256; k += 4) {
            const float s0 = sdm[(k + 0) * NB + lane];
            const float s1 = sdm[(k + 1) * NB + lane];
            const float s2 = sdm[(k + 2) * NB + lane];
            const float s3 = sdm[(k + 3) * NB + lane];
            #pragma unroll
            for (int j = 0; j < 4; j++) {
                const float4 d = *(const float4*)&sDT[(r0 + j) * DT_STRIDE + k];
                acc[j] += d.x * s0 + d.y * s1 + d.z * s2 + d.w * s3;
            }
        }
        #pragma unroll
        for (int j = 0; j < 4; j++) sbq[(r0 + j) * NB + lane] = eta * acc[j];
    }
    __syncthreads();

    for (int it = 0; it < T_ITERS; it++) {
        // ---- phase 1: threshold + delta --------------------------------
        #pragma unroll
        for (int r = wid; r < 64; r += NWARP) {
            const int idx = r * NB + lane;
            const float zn = fmaxf(0.f, sbq[idx]);
            sdq[idx] = zn - sZq[idx];
            sZq[idx] = zn;
        }
        #pragma unroll
        for (int r = wid; r < 256; r += NWARP) {
            const int idx = r * NB + lane;
            const float zn = fmaxf(0.f, sbm[idx] - thr);
            sdm[idx] = zn - sZm[idx];
            sZm[idx] = zn;
        }
        __syncthreads();

        if (it == T_ITERS - 1) break;   // final b-update is dead

        // ---- phase A: w = D @ dq ; b_m update ; s = w + dv in place ----
        {
            const int r0 = wid * 16;
            float acc[16];
            #pragma unroll
            for (int j = 0; j < 16; j++) acc[j] = 0.f;

            #pragma unroll 4
            for (int k = 0; k < 64; k++) {
                const float dval = sdq[k * NB + lane];
                const float4* dp = (const float4*)&sDT[k * DT_STRIDE + r0];
                const float4 a0 = dp[0], a1 = dp[1], a2 = dp[2], a3 = dp[3];
                acc[0]  += a0.x * dval; acc[1]  += a0.y * dval;
                acc[2]  += a0.z * dval; acc[3]  += a0.w * dval;
                acc[4]  += a1.x * dval; acc[5]  += a1.y * dval;
                acc[6]  += a1.z * dval; acc[7]  += a1.w * dval;
                acc[8]  += a2.x * dval; acc[9]  += a2.y * dval;
                acc[10] += a2.z * dval; acc[11] += a2.w * dval;
                acc[12] += a3.x * dval; acc[13] += a3.y * dval;
                acc[14] += a3.z * dval; acc[15] += a3.w * dval;
            }
            #pragma unroll
            for (int j = 0; j < 16; j++) {
                const int idx = (r0 + j) * NB + lane;
                const float dvv = sdm[idx];
                const float w = acc[j];
                sbm[idx] += cm * dvv - eta * w;
                sdm[idx] = w + dvv;            // s = D*du + dv
            }
        }
        __syncthreads();

        // ---- phase B: y = D^T @ s ; b_q update -------------------------
        {
            const int r0 = wid * 4;
            float acc[4] = {0.f, 0.f, 0.f, 0.f};
            #pragma unroll 2
            for (int k = 0; k < 256; k += 4) {
                const float s0 = sdm[(k + 0) * NB + lane];
                const float s1 = sdm[(k + 1) * NB + lane];
                const float s2 = sdm[(k + 2) * NB + lane];
                const float s3 = sdm[(k + 3) * NB + lane];
                #pragma unroll
                for (int j = 0; j < 4; j++) {
                    const float4 d = *(const float4*)&sDT[(r0 + j) * DT_STRIDE + k];
                    acc[j] += d.x * s0 + d.y * s1 + d.z * s2 + d.w * s3;
                }
            }
            #pragma unroll
            for (int j = 0; j < 4; j++) {
                const int idx = (r0 + j) * NB + lane;
                sbq[idx] += cq * sdq[idx] - eta * acc[j];
            }
        }
        __syncthreads();
    }

    // ---- output: Z = [Z_q ; Z_m], row-major [320, 65536] ----------------
    for (int r = wid; r < 64; r += NWARP)
        out[(size_t)r * N_DIM + col0 + lane] = sZq[r * NB + lane];
    for (int r = wid; r < 256; r += NWARP)
        out[(size_t)(64 + r) * N_DIM + col0 + lane] = sZm[r * NB + lane];
}

// ---------------------------------------------------------------------------
// Launch
// ---------------------------------------------------------------------------
extern "C" void kernel_launch(void* const* d_in, const int* in_sizes, int n_in,
                              void* d_out, int out_size)
{
    const float* X = (const float*)d_in[0];
    const float* D = (const float*)d_in[1];
    // Defensive: identify by size (X has 256*65536 elems, D has 256*64)
    if (n_in >= 2 && in_sizes[0] == M_DIM * Q_DIM) {
        X = (const float*)d_in[1];
        D = (const float*)d_in[0];
    }
    float* out = (float*)d_out;

    const size_t prep_smem = (size_t)(256 * 64 + 64 * 64 + 64 + 64 + 2) * sizeof(float);
    const size_t main_smem = (size_t)(64 * DT_STRIDE + 3 * 64 * NB + 3 * 256 * NB) * sizeof(float);

    cudaFuncSetAttribute(prep_kernel, cudaFuncAttributeMaxDynamicSharedMemorySize,
                         (int)prep_smem);
    cudaFuncSetAttribute(ista_kernel, cudaFuncAttributeMaxDynamicSharedMemorySize,
                         (int)main_smem);

    prep_kernel<<<1, 256, prep_smem>>>(D);
    ista_kernel<<<N_DIM / NB, THREADS, main_smem>>>(X, D, out);
}

// round 5
// speedup vs baseline: 1.0006x; 1.0006x over previous
#include <cuda_runtime.h>
#include <math.h>

// Problem constants
#define M_DIM 256
#define Q_DIM 64
#define N_DIM 65536
#define NB 32            // columns per CTA (== warp size; lane = column)
#define THREADS 512
#define NWARP 16
#define T_ITERS 16
#define PM_ITERS 200
#define LAMBDA_STAR 0.1f
#define LAMBDA_O 0.1f
#define DT_STRIDE 260    // 256 + 4 pad (bank-conflict relief, keeps 16B alignment)

// eta, thr, c_q, c_m
__device__ float g_consts[4];

// ---------------------------------------------------------------------------
// Prep: G = D^T D, power iteration for alpha = lambda_max(G), derive constants.
// Single block, 256 threads.
// ---------------------------------------------------------------------------
__global__ void prep_kernel(const float* __restrict__ D)
{
    extern __shared__ float sm[];
    float* sD   = sm;                 // [256][64]
    float* sG   = sD + 256 * 64;      // [64][64]
    float* sx   = sG + 64 * 64;       // [64]
    float* sy   = sx + 64;            // [64]
    float* sred = sy + 64;            // [2]

    const int t = threadIdx.x;

    for (int i = t; i < 256 * 64; i += blockDim.x) sD[i] = D[i];
    __syncthreads();

    // G = D^T D : each thread computes a 4x4 block (16x16 grid of blocks)
    {
        const int bi = t & 15, bj = t >> 4;
        const int i0 = bi * 4, j0 = bj * 4;
        float acc[4][4];
        #pragma unroll
        for (int a = 0; a < 4; a++)
            #pragma unroll
            for (int b = 0; b < 4; b++) acc[a][b] = 0.f;

        for (int k = 0; k < 256; k++) {
            const float4 av = *(const float4*)&sD[k * 64 + i0];
            const float4 bv = *(const float4*)&sD[k * 64 + j0];
            const float ai[4] = {av.x, av.y, av.z, av.w};
            const float bjv[4] = {bv.x, bv.y, bv.z, bv.w};
            #pragma unroll
            for (int a = 0; a < 4; a++)
                #pragma unroll
                for (int b = 0; b < 4; b++) acc[a][b] += ai[a] * bjv[b];
        }
        #pragma unroll
        for (int a = 0; a < 4; a++)
            #pragma unroll
            for (int b = 0; b < 4; b++) sG[(i0 + a) * 64 + (j0 + b)] = acc[a][b];
    }

    if (t < 64) sx[t] = 1.0f;
    __syncthreads();

    float alpha = 0.f;
    for (int it = 0; it < PM_ITERS; it++) {
        if (t < 64) {
            const float* g = &sG[t * 64];
            float y = 0.f;
            #pragma unroll 8
            for (int j = 0; j < 64; j++) y += g[j] * sx[j];
            sy[t] = y;
        }
        __syncthreads();

        float ss = 0.f;
        if (t < 64) { float y = sy[t]; ss = y * y; }
        #pragma unroll
        for (int off = 16; off > 0; off >>= 1)
            ss += __shfl_down_sync(0xffffffffu, ss, off);
        if (t < 64 && (t & 31) == 0) sred[t >> 5] = ss;
        __syncthreads();

        const float nm = sqrtf(sred[0] + sred[1]);
        if (t < 64) sx[t] = sy[t] / nm;
        alpha = nm;
        __syncthreads();
    }

    if (t == 0) {
        const float eta = 1.0f / alpha;
        g_consts[0] = eta;
        g_consts[1] = LAMBDA_O * eta;                       // threshold (m rows)
        g_consts[2] = 1.0f - eta * LAMBDA_STAR;             // c_q
        g_consts[3] = 1.0f - eta * (1.0f + LAMBDA_STAR);    // c_m
    }
}

// ---------------------------------------------------------------------------
// Main ISTA kernel. One CTA = 32 columns (lane = column), state in SMEM:
//   b = [b_q(64); b_m(256)], Z likewise, per iteration:
//     Znew = relu(b - t); d = Znew - Z; Z = Znew
//     w = D @ d_q                 (256 x 32)
//     b_m += c_m*d_m - eta*w;  s = w + d_m  (stored in place of d_m)
//     y = D^T @ s                 (64 x 32)
//     b_q += c_q*d_q - eta*y
//   (last iteration skips the b-update; it is dead in the reference scan)
// ---------------------------------------------------------------------------
__global__ void __launch_bounds__(THREADS)
ista_kernel(const float* __restrict__ X, const float* __restrict__ D,
            float* __restrict__ out)
{
    extern __shared__ float sm[];
    float* sDT = sm;                        // [64][DT_STRIDE]  D^T (padded)
    float* sbq = sDT + 64 * DT_STRIDE;      // [64][32]
    float* sZq = sbq + 64 * NB;             // [64][32]
    float* sdq = sZq + 64 * NB;             // [64][32]
    float* sbm = sdq + 64 * NB;             // [256][32]
    float* sZm = sbm + 256 * NB;            // [256][32]
    float* sdm = sZm + 256 * NB;            // [256][32]  (dv, then s = w+dv)

    const int tid  = threadIdx.x;
    const int lane = tid & 31;
    const int wid  = tid >> 5;
    const int col0 = blockIdx.x * NB;

    const float eta = g_consts[0];
    const float thr = g_consts[1];
    const float cq  = g_consts[2];
    const float cm  = g_consts[3];

    // Load D transposed: sDT[q][k] = D[k][q]
    for (int k = wid; k < 256; k += NWARP) {
        #pragma unroll
        for (int q = lane; q < 64; q += 32)
            sDT[q * DT_STRIDE + k] = D[k * 64 + q];
    }

    // Load X tile; init b_m = eta*x, Z = 0; stash x in sdm for the b_q GEMV
    for (int r = wid; r < 256; r += NWARP) {
        const float x = X[(size_t)r * N_DIM + col0 + lane];
        const int idx = r * NB + lane;
        sdm[idx] = x;
        sbm[idx] = eta * x;
        sZm[idx] = 0.f;
    }
    for (int r = wid; r < 64; r += NWARP) sZq[r * NB + lane] = 0.f;
    __syncthreads();

    // b_q = eta * D^T x   (4 rows per warp)
    {
        const int r0 = wid * 4;
        float acc[4] = {0.f, 0.f, 0.f, 0.f};
        for (int k = 0; k < 256; k += 4) {
            const float s0 = sdm[(k + 0) * NB + lane];
            const float s1 = sdm[(k + 1) * NB + lane];
            const float s2 = sdm[(k + 2) * NB + lane];
            const float s3 = sdm[(k + 3) * NB + lane];
            #pragma unroll
            for (int j = 0; j < 4; j++) {
                const float4 d = *(const float4*)&sDT[(r0 + j) * DT_STRIDE + k];
                acc[j] += d.x * s0 + d.y * s1 + d.z * s2 + d.w * s3;
            }
        }
        #pragma unroll
        for (int j = 0; j < 4; j++) sbq[(r0 + j) * NB + lane] = eta * acc[j];
    }
    __syncthreads();

    for (int it = 0; it < T_ITERS; it++) {
        // ---- phase 1: threshold + delta --------------------------------
        #pragma unroll
        for (int r = wid; r < 64; r += NWARP) {
            const int idx = r * NB + lane;
            const float zn = fmaxf(0.f, sbq[idx]);
            sdq[idx] = zn - sZq[idx];
            sZq[idx] = zn;
        }
        #pragma unroll
        for (int r = wid; r < 256; r += NWARP) {
            const int idx = r * NB + lane;
            const float zn = fmaxf(0.f, sbm[idx] - thr);
            sdm[idx] = zn - sZm[idx];
            sZm[idx] = zn;
        }
        __syncthreads();

        if (it == T_ITERS - 1) break;   // final b-update is dead

        // ---- phase A: w = D @ dq ; b_m update ; s = w + dv in place ----
        {
            const int r0 = wid * 16;
            float acc[16];
            #pragma unroll
            for (int j = 0; j < 16; j++) acc[j] = 0.f;

            #pragma unroll 4
            for (int k = 0; k < 64; k++) {
                const float dval = sdq[k * NB + lane];
                const float4* dp = (const float4*)&sDT[k * DT_STRIDE + r0];
                const float4 a0 = dp[0], a1 = dp[1], a2 = dp[2], a3 = dp[3];
                acc[0]  += a0.x * dval; acc[1]  += a0.y * dval;
                acc[2]  += a0.z * dval; acc[3]  += a0.w * dval;
                acc[4]  += a1.x * dval; acc[5]  += a1.y * dval;
                acc[6]  += a1.z * dval; acc[7]  += a1.w * dval;
                acc[8]  += a2.x * dval; acc[9]  += a2.y * dval;
                acc[10] += a2.z * dval; acc[11] += a2.w * dval;
                acc[12] += a3.x * dval; acc[13] += a3.y * dval;
                acc[14] += a3.z * dval; acc[15] += a3.w * dval;
            }
            #pragma unroll
            for (int j = 0; j < 16; j++) {
                const int idx = (r0 + j) * NB + lane;
                const float dvv = sdm[idx];
                const float w = acc[j];
                sbm[idx] += cm * dvv - eta * w;
                sdm[idx] = w + dvv;            // s = D*du + dv
            }
        }
        __syncthreads();

        // ---- phase B: y = D^T @ s ; b_q update -------------------------
        {
            const int r0 = wid * 4;
            float acc[4] = {0.f, 0.f, 0.f, 0.f};
            #pragma unroll 2
            for (int k = 0; k < 256; k += 4) {
                const float s0 = sdm[(k + 0) * NB + lane];
                const float s1 = sdm[(k + 1) * NB + lane];
                const float s2 = sdm[(k + 2) * NB + lane];
                const float s3 = sdm[(k + 3) * NB + lane];
                #pragma unroll
                for (int j = 0; j < 4; j++) {
                    const float4 d = *(const float4*)&sDT[(r0 + j) * DT_STRIDE + k];
                    acc[j] += d.x * s0 + d.y * s1 + d.z * s2 + d.w * s3;
                }
            }
            #pragma unroll
            for (int j = 0; j < 4; j++) {
                const int idx = (r0 + j) * NB + lane;
                sbq[idx] += cq * sdq[idx] - eta * acc[j];
            }
        }
        __syncthreads();
    }

    // ---- output: Z = [Z_q ; Z_m], row-major [320, 65536] ----------------
    for (int r = wid; r < 64; r += NWARP)
        out[(size_t)r * N_DIM + col0 + lane] = sZq[r * NB + lane];
    for (int r = wid; r < 256; r += NWARP)
        out[(size_t)(64 + r) * N_DIM + col0 + lane] = sZm[r * NB + lane];
}

// ---------------------------------------------------------------------------
// Launch
// ---------------------------------------------------------------------------
extern "C" void kernel_launch(void* const* d_in, const int* in_sizes, int n_in,
                              void* d_out, int out_size)
{
    const float* X = (const float*)d_in[0];
    const float* D = (const float*)d_in[1];
    // Defensive: identify by size (X has 256*65536 elems, D has 256*64)
    if (n_in >= 2 && in_sizes[0] == M_DIM * Q_DIM) {
        X = (const float*)d_in[1];
        D = (const float*)d_in[0];
    }
    float* out = (float*)d_out;

    const size_t prep_smem = (size_t)(256 * 64 + 64 * 64 + 64 + 64 + 2) * sizeof(float);
    const size_t main_smem = (size_t)(64 * DT_STRIDE + 3 * 64 * NB + 3 * 256 * NB) * sizeof(float);

    cudaFuncSetAttribute(prep_kernel, cudaFuncAttributeMaxDynamicSharedMemorySize,
                         (int)prep_smem);
    cudaFuncSetAttribute(ista_kernel, cudaFuncAttributeMaxDynamicSharedMemorySize,
                         (int)main_smem);

    prep_kernel<<<1, 256, prep_smem>>>(D);
    ista_kernel<<<N_DIM / NB, THREADS, main_smem>>>(X, D, out);
}

// round 6
// speedup vs baseline: 1.0012x; 1.0005x over previous
#include <cuda_runtime.h>
#include <math.h>

// Problem constants
#define M_DIM 256
#define Q_DIM 64
#define N_DIM 65536
#define NB 32            // columns per CTA (== warp size; lane = column)
#define THREADS 512
#define NWARP 16
#define T_ITERS 16
#define PM_ITERS 200
#define LAMBDA_STAR 0.1f
#define LAMBDA_O 0.1f
#define DT_STRIDE 260    // 256 + 4 pad (bank-conflict relief, keeps 16B alignment)

// eta, thr, c_q, c_m
__device__ float g_consts[4];

// ---------------------------------------------------------------------------
// Prep: G = D^T D, power iteration for alpha = lambda_max(G), derive constants.
// Single block, 256 threads.
// ---------------------------------------------------------------------------
__global__ void prep_kernel(const float* __restrict__ D)
{
    extern __shared__ float sm[];
    float* sD   = sm;                 // [256][64]
    float* sG   = sD + 256 * 64;      // [64][64]
    float* sx   = sG + 64 * 64;       // [64]
    float* sy   = sx + 64;            // [64]
    float* sred = sy + 64;            // [2]

    const int t = threadIdx.x;

    for (int i = t; i < 256 * 64; i += blockDim.x) sD[i] = D[i];
    __syncthreads();

    // G = D^T D : each thread computes a 4x4 block (16x16 grid of blocks)
    {
        const int bi = t & 15, bj = t >> 4;
        const int i0 = bi * 4, j0 = bj * 4;
        float acc[4][4];
        #pragma unroll
        for (int a = 0; a < 4; a++)
            #pragma unroll
            for (int b = 0; b < 4; b++) acc[a][b] = 0.f;

        for (int k = 0; k < 256; k++) {
            const float4 av = *(const float4*)&sD[k * 64 + i0];
            const float4 bv = *(const float4*)&sD[k * 64 + j0];
            const float ai[4] = {av.x, av.y, av.z, av.w};
            const float bjv[4] = {bv.x, bv.y, bv.z, bv.w};
            #pragma unroll
            for (int a = 0; a < 4; a++)
                #pragma unroll
                for (int b = 0; b < 4; b++) acc[a][b] += ai[a] * bjv[b];
        }
        #pragma unroll
        for (int a = 0; a < 4; a++)
            #pragma unroll
            for (int b = 0; b < 4; b++) sG[(i0 + a) * 64 + (j0 + b)] = acc[a][b];
    }

    if (t < 64) sx[t] = 1.0f;
    __syncthreads();

    float alpha = 0.f;
    for (int it = 0; it < PM_ITERS; it++) {
        if (t < 64) {
            const float* g = &sG[t * 64];
            float y = 0.f;
            #pragma unroll 8
            for (int j = 0; j < 64; j++) y += g[j] * sx[j];
            sy[t] = y;
        }
        __syncthreads();

        float ss = 0.f;
        if (t < 64) { float y = sy[t]; ss = y * y; }
        #pragma unroll
        for (int off = 16; off > 0; off >>= 1)
            ss += __shfl_down_sync(0xffffffffu, ss, off);
        if (t < 64 && (t & 31) == 0) sred[t >> 5] = ss;
        __syncthreads();

        const float nm = sqrtf(sred[0] + sred[1]);
        if (t < 64) sx[t] = sy[t] / nm;
        alpha = nm;
        __syncthreads();
    }

    if (t == 0) {
        const float eta = 1.0f / alpha;
        g_consts[0] = eta;
        g_consts[1] = LAMBDA_O * eta;                       // threshold (m rows)
        g_consts[2] = 1.0f - eta * LAMBDA_STAR;             // c_q
        g_consts[3] = 1.0f - eta * (1.0f + LAMBDA_STAR);    // c_m
    }
}

// ---------------------------------------------------------------------------
// Main ISTA kernel. One CTA = 32 columns (lane = column), state in SMEM:
//   b = [b_q(64); b_m(256)], Z likewise, per iteration:
//     Znew = relu(b - t); d = Znew - Z; Z = Znew
//     w = D @ d_q                 (256 x 32)
//     b_m += c_m*d_m - eta*w;  s = w + d_m  (stored in place of d_m)
//     y = D^T @ s                 (64 x 32)
//     b_q += c_q*d_q - eta*y
//   (last iteration skips the b-update; it is dead in the reference scan)
// ---------------------------------------------------------------------------
__global__ void __launch_bounds__(THREADS)
ista_kernel(const float* __restrict__ X, const float* __restrict__ D,
            float* __restrict__ out)
{
    extern __shared__ float sm[];
    float* sDT = sm;                        // [64][DT_STRIDE]  D^T (padded)
    float* sbq = sDT + 64 * DT_STRIDE;      // [64][32]
    float* sZq = sbq + 64 * NB;             // [64][32]
    float* sdq = sZq + 64 * NB;             // [64][32]
    float* sbm = sdq + 64 * NB;             // [256][32]
    float* sZm = sbm + 256 * NB;            // [256][32]
    float* sdm = sZm + 256 * NB;            // [256][32]  (dv, then s = w+dv)

    const int tid  = threadIdx.x;
    const int lane = tid & 31;
    const int wid  = tid >> 5;
    const int col0 = blockIdx.x * NB;

    const float eta = g_consts[0];
    const float thr = g_consts[1];
    const float cq  = g_consts[2];
    const float cm  = g_consts[3];

    // Load D transposed: sDT[q][k] = D[k][q]
    for (int k = wid; k < 256; k += NWARP) {
        #pragma unroll
        for (int q = lane; q < 64; q += 32)
            sDT[q * DT_STRIDE + k] = D[k * 64 + q];
    }

    // Load X tile; init b_m = eta*x, Z = 0; stash x in sdm for the b_q GEMV
    for (int r = wid; r < 256; r += NWARP) {
        const float x = X[(size_t)r * N_DIM + col0 + lane];
        const int idx = r * NB + lane;
        sdm[idx] = x;
        sbm[idx] = eta * x;
        sZm[idx] = 0.f;
    }
    for (int r = wid; r < 64; r += NWARP) sZq[r * NB + lane] = 0.f;
    __syncthreads();

    // b_q = eta * D^T x   (4 rows per warp)
    {
        const int r0 = wid * 4;
        float acc[4] = {0.f, 0.f, 0.f, 0.f};
        for (int k = 0; k < 256; k += 4) {
            const float s0 = sdm[(k + 0) * NB + lane];
            const float s1 = sdm[(k + 1) * NB + lane];
            const float s2 = sdm[(k + 2) * NB + lane];
            const float s3 = sdm[(k + 3) * NB + lane];
            #pragma unroll
            for (int j = 0; j < 4; j++) {
                const float4 d = *(const float4*)&sDT[(r0 + j) * DT_STRIDE + k];
                acc[j] += d.x * s0 + d.y * s1 + d.z * s2 + d.w * s3;
            }
        }
        #pragma unroll
        for (int j = 0; j < 4; j++) sbq[(r0 + j) * NB + lane] = eta * acc[j];
    }
    __syncthreads();

    for (int it = 0; it < T_ITERS; it++) {
        // ---- phase 1: threshold + delta --------------------------------
        #pragma unroll
        for (int r = wid; r < 64; r += NWARP) {
            const int idx = r * NB + lane;
            const float zn = fmaxf(0.f, sbq[idx]);
            sdq[idx] = zn - sZq[idx];
            sZq[idx] = zn;
        }
        #pragma unroll
        for (int r = wid; r < 256; r += NWARP) {
            const int idx = r * NB + lane;
            const float zn = fmaxf(0.f, sbm[idx] - thr);
            sdm[idx] = zn - sZm[idx];
            sZm[idx] = zn;
        }
        __syncthreads();

        if (it == T_ITERS - 1) break;   // final b-update is dead

        // ---- phase A: w = D @ dq ; b_m update ; s = w + dv in place ----
        {
            const int r0 = wid * 16;
            float acc[16];
            #pragma unroll
            for (int j = 0; j < 16; j++) acc[j] = 0.f;

            #pragma unroll 4
            for (int k = 0; k < 64; k++) {
                const float dval = sdq[k * NB + lane];
                const float4* dp = (const float4*)&sDT[k * DT_STRIDE + r0];
                const float4 a0 = dp[0], a1 = dp[1], a2 = dp[2], a3 = dp[3];
                acc[0]  += a0.x * dval; acc[1]  += a0.y * dval;
                acc[2]  += a0.z * dval; acc[3]  += a0.w * dval;
                acc[4]  += a1.x * dval; acc[5]  += a1.y * dval;
                acc[6]  += a1.z * dval; acc[7]  += a1.w * dval;
                acc[8]  += a2.x * dval; acc[9]  += a2.y * dval;
                acc[10] += a2.z * dval; acc[11] += a2.w * dval;
                acc[12] += a3.x * dval; acc[13] += a3.y * dval;
                acc[14] += a3.z * dval; acc[15] += a3.w * dval;
            }
            #pragma unroll
            for (int j = 0; j < 16; j++) {
                const int idx = (r0 + j) * NB + lane;
                const float dvv = sdm[idx];
                const float w = acc[j];
                sbm[idx] += cm * dvv - eta * w;
                sdm[idx] = w + dvv;            // s = D*du + dv
            }
        }
        __syncthreads();

        // ---- phase B: y = D^T @ s ; b_q update -------------------------
        {
            const int r0 = wid * 4;
            float acc[4] = {0.f, 0.f, 0.f, 0.f};
            #pragma unroll 2
            for (int k = 0; k < 256; k += 4) {
                const float s0 = sdm[(k + 0) * NB + lane];
                const float s1 = sdm[(k + 1) * NB + lane];
                const float s2 = sdm[(k + 2) * NB + lane];
                const float s3 = sdm[(k + 3) * NB + lane];
                #pragma unroll
                for (int j = 0; j < 4; j++) {
                    const float4 d = *(const float4*)&sDT[(r0 + j) * DT_STRIDE + k];
                    acc[j] += d.x * s0 + d.y * s1 + d.z * s2 + d.w * s3;
                }
            }
            #pragma unroll
            for (int j = 0; j < 4; j++) {
                const int idx = (r0 + j) * NB + lane;
                sbq[idx] += cq * sdq[idx] - eta * acc[j];
            }
        }
        __syncthreads();
    }

    // ---- output: Z = [Z_q ; Z_m], row-major [320, 65536] ----------------
    for (int r = wid; r < 64; r += NWARP)
        out[(size_t)r * N_DIM + col0 + lane] = sZq[r * NB + lane];
    for (int r = wid; r < 256; r += NWARP)
        out[(size_t)(64 + r) * N_DIM + col0 + lane] = sZm[r * NB + lane];
}

// ---------------------------------------------------------------------------
// Launch
// ---------------------------------------------------------------------------
extern "C" void kernel_launch(void* const* d_in, const int* in_sizes, int n_in,
                              void* d_out, int out_size)
{
    const float* X = (const float*)d_in[0];
    const float* D = (const float*)d_in[1];
    // Defensive: identify by size (X has 256*65536 elems, D has 256*64)
    if (n_in >= 2 && in_sizes[0] == M_DIM * Q_DIM) {
        X = (const float*)d_in[1];
        D = (const float*)d_in[0];
    }
    float* out = (float*)d_out;

    const size_t prep_smem = (size_t)(256 * 64 + 64 * 64 + 64 + 64 + 2) * sizeof(float);
    const size_t main_smem = (size_t)(64 * DT_STRIDE + 3 * 64 * NB + 3 * 256 * NB) * sizeof(float);

    cudaFuncSetAttribute(prep_kernel, cudaFuncAttributeMaxDynamicSharedMemorySize,
                         (int)prep_smem);
    cudaFuncSetAttribute(ista_kernel, cudaFuncAttributeMaxDynamicSharedMemorySize,
                         (int)main_smem);

    prep_kernel<<<1, 256, prep_smem>>>(D);
    ista_kernel<<<N_DIM / NB, THREADS, main_smem>>>(X, D, out);
}

// round 7
// speedup vs baseline: 1.0014x; 1.0003x over previous
#include <cuda_runtime.h>
#include <math.h>

// Problem constants
#define M_DIM 256
#define Q_DIM 64
#define N_DIM 65536
#define NB 32            // columns per CTA (== warp size; lane = column)
#define THREADS 512
#define NWARP 16
#define T_ITERS 16
#define PM_ITERS 200
#define LAMBDA_STAR 0.1f
#define LAMBDA_O 0.1f
#define DT_STRIDE 260    // 256 + 4 pad (bank-conflict relief, keeps 16B alignment)

// eta, thr, c_q, c_m
__device__ float g_consts[4];

// ---------------------------------------------------------------------------
// Prep: G = D^T D, power iteration for alpha = lambda_max(G), derive constants.
// Single block, 256 threads.
// ---------------------------------------------------------------------------
__global__ void prep_kernel(const float* __restrict__ D)
{
    extern __shared__ float sm[];
    float* sD   = sm;                 // [256][64]
    float* sG   = sD + 256 * 64;      // [64][64]
    float* sx   = sG + 64 * 64;       // [64]
    float* sy   = sx + 64;            // [64]
    float* sred = sy + 64;            // [2]

    const int t = threadIdx.x;

    for (int i = t; i < 256 * 64; i += blockDim.x) sD[i] = D[i];
    __syncthreads();

    // G = D^T D : each thread computes a 4x4 block (16x16 grid of blocks)
    {
        const int bi = t & 15, bj = t >> 4;
        const int i0 = bi * 4, j0 = bj * 4;
        float acc[4][4];
        #pragma unroll
        for (int a = 0; a < 4; a++)
            #pragma unroll
            for (int b = 0; b < 4; b++) acc[a][b] = 0.f;

        for (int k = 0; k < 256; k++) {
            const float4 av = *(const float4*)&sD[k * 64 + i0];
            const float4 bv = *(const float4*)&sD[k * 64 + j0];
            const float ai[4] = {av.x, av.y, av.z, av.w};
            const float bjv[4] = {bv.x, bv.y, bv.z, bv.w};
            #pragma unroll
            for (int a = 0; a < 4; a++)
                #pragma unroll
                for (int b = 0; b < 4; b++) acc[a][b] += ai[a] * bjv[b];
        }
        #pragma unroll
        for (int a = 0; a < 4; a++)
            #pragma unroll
            for (int b = 0; b < 4; b++) sG[(i0 + a) * 64 + (j0 + b)] = acc[a][b];
    }

    if (t < 64) sx[t] = 1.0f;
    __syncthreads();

    float alpha = 0.f;
    for (int it = 0; it < PM_ITERS; it++) {
        if (t < 64) {
            const float* g = &sG[t * 64];
            float y = 0.f;
            #pragma unroll 8
            for (int j = 0; j < 64; j++) y += g[j] * sx[j];
            sy[t] = y;
        }
        __syncthreads();

        float ss = 0.f;
        if (t < 64) { float y = sy[t]; ss = y * y; }
        #pragma unroll
        for (int off = 16; off > 0; off >>= 1)
            ss += __shfl_down_sync(0xffffffffu, ss, off);
        if (t < 64 && (t & 31) == 0) sred[t >> 5] = ss;
        __syncthreads();

        const float nm = sqrtf(sred[0] + sred[1]);
        if (t < 64) sx[t] = sy[t] / nm;
        alpha = nm;
        __syncthreads();
    }

    if (t == 0) {
        const float eta = 1.0f / alpha;
        g_consts[0] = eta;
        g_consts[1] = LAMBDA_O * eta;                       // threshold (m rows)
        g_consts[2] = 1.0f - eta * LAMBDA_STAR;             // c_q
        g_consts[3] = 1.0f - eta * (1.0f + LAMBDA_STAR);    // c_m
    }
}

// ---------------------------------------------------------------------------
// Main ISTA kernel. One CTA = 32 columns (lane = column), state in SMEM:
//   b = [b_q(64); b_m(256)], Z likewise, per iteration:
//     Znew = relu(b - t); d = Znew - Z; Z = Znew
//     w = D @ d_q                 (256 x 32)
//     b_m += c_m*d_m - eta*w;  s = w + d_m  (stored in place of d_m)
//     y = D^T @ s                 (64 x 32)
//     b_q += c_q*d_q - eta*y
//   (last iteration skips the b-update; it is dead in the reference scan)
// ---------------------------------------------------------------------------
__global__ void __launch_bounds__(THREADS)
ista_kernel(const float* __restrict__ X, const float* __restrict__ D,
            float* __restrict__ out)
{
    extern __shared__ float sm[];
    float* sDT = sm;                        // [64][DT_STRIDE]  D^T (padded)
    float* sbq = sDT + 64 * DT_STRIDE;      // [64][32]
    float* sZq = sbq + 64 * NB;             // [64][32]
    float* sdq = sZq + 64 * NB;             // [64][32]
    float* sbm = sdq + 64 * NB;             // [256][32]
    float* sZm = sbm + 256 * NB;            // [256][32]
    float* sdm = sZm + 256 * NB;            // [256][32]  (dv, then s = w+dv)

    const int tid  = threadIdx.x;
    const int lane = tid & 31;
    const int wid  = tid >> 5;
    const int col0 = blockIdx.x * NB;

    const float eta = g_consts[0];
    const float thr = g_consts[1];
    const float cq  = g_consts[2];
    const float cm  = g_consts[3];

    // Load D transposed: sDT[q][k] = D[k][q]
    for (int k = wid; k < 256; k += NWARP) {
        #pragma unroll
        for (int q = lane; q < 64; q += 32)
            sDT[q * DT_STRIDE + k] = D[k * 64 + q];
    }

    // Load X tile; init b_m = eta*x, Z = 0; stash x in sdm for the b_q GEMV
    for (int r = wid; r < 256; r += NWARP) {
        const float x = X[(size_t)r * N_DIM + col0 + lane];
        const int idx = r * NB + lane;
        sdm[idx] = x;
        sbm[idx] = eta * x;
        sZm[idx] = 0.f;
    }
    for (int r = wid; r < 64; r += NWARP) sZq[r * NB + lane] = 0.f;
    __syncthreads();

    // b_q = eta * D^T x   (4 rows per warp)
    {
        const int r0 = wid * 4;
        float acc[4] = {0.f, 0.f, 0.f, 0.f};
        for (int k = 0; k < 256; k += 4) {
            const float s0 = sdm[(k + 0) * NB + lane];
            const float s1 = sdm[(k + 1) * NB + lane];
            const float s2 = sdm[(k + 2) * NB + lane];
            const float s3 = sdm[(k + 3) * NB + lane];
            #pragma unroll
            for (int j = 0; j < 4; j++) {
                const float4 d = *(const float4*)&sDT[(r0 + j) * DT_STRIDE + k];
                acc[j] += d.x * s0 + d.y * s1 + d.z * s2 + d.w * s3;
            }
        }
        #pragma unroll
        for (int j = 0; j < 4; j++) sbq[(r0 + j) * NB + lane] = eta * acc[j];
    }
    __syncthreads();

    for (int it = 0; it < T_ITERS; it++) {
        // ---- phase 1: threshold + delta --------------------------------
        #pragma unroll
        for (int r = wid; r < 64; r += NWARP) {
            const int idx = r * NB + lane;
            const float zn = fmaxf(0.f, sbq[idx]);
            sdq[idx] = zn - sZq[idx];
            sZq[idx] = zn;
        }
        #pragma unroll
        for (int r = wid; r < 256; r += NWARP) {
            const int idx = r * NB + lane;
            const float zn = fmaxf(0.f, sbm[idx] - thr);
            sdm[idx] = zn - sZm[idx];
            sZm[idx] = zn;
        }
        __syncthreads();

        if (it == T_ITERS - 1) break;   // final b-update is dead

        // ---- phase A: w = D @ dq ; b_m update ; s = w + dv in place ----
        {
            const int r0 = wid * 16;
            float acc[16];
            #pragma unroll
            for (int j = 0; j < 16; j++) acc[j] = 0.f;

            #pragma unroll 4
            for (int k = 0; k < 64; k++) {
                const float dval = sdq[k * NB + lane];
                const float4* dp = (const float4*)&sDT[k * DT_STRIDE + r0];
                const float4 a0 = dp[0], a1 = dp[1], a2 = dp[2], a3 = dp[3];
                acc[0]  += a0.x * dval; acc[1]  += a0.y * dval;
                acc[2]  += a0.z * dval; acc[3]  += a0.w * dval;
                acc[4]  += a1.x * dval; acc[5]  += a1.y * dval;
                acc[6]  += a1.z * dval; acc[7]  += a1.w * dval;
                acc[8]  += a2.x * dval; acc[9]  += a2.y * dval;
                acc[10] += a2.z * dval; acc[11] += a2.w * dval;
                acc[12] += a3.x * dval; acc[13] += a3.y * dval;
                acc[14] += a3.z * dval; acc[15] += a3.w * dval;
            }
            #pragma unroll
            for (int j = 0; j < 16; j++) {
                const int idx = (r0 + j) * NB + lane;
                const float dvv = sdm[idx];
                const float w = acc[j];
                sbm[idx] += cm * dvv - eta * w;
                sdm[idx] = w + dvv;            // s = D*du + dv
            }
        }
        __syncthreads();

        // ---- phase B: y = D^T @ s ; b_q update -------------------------
        {
            const int r0 = wid * 4;
            float acc[4] = {0.f, 0.f, 0.f, 0.f};
            #pragma unroll 2
            for (int k = 0; k < 256; k += 4) {
                const float s0 = sdm[(k + 0) * NB + lane];
                const float s1 = sdm[(k + 1) * NB + lane];
                const float s2 = sdm[(k + 2) * NB + lane];
                const float s3 = sdm[(k + 3) * NB + lane];
                #pragma unroll
                for (int j = 0; j < 4; j++) {
                    const float4 d = *(const float4*)&sDT[(r0 + j) * DT_STRIDE + k];
                    acc[j] += d.x * s0 + d.y * s1 + d.z * s2 + d.w * s3;
                }
            }
            #pragma unroll
            for (int j = 0; j < 4; j++) {
                const int idx = (r0 + j) * NB + lane;
                sbq[idx] += cq * sdq[idx] - eta * acc[j];
            }
        }
        __syncthreads();
    }

    // ---- output: Z = [Z_q ; Z_m], row-major [320, 65536] ----------------
    for (int r = wid; r < 64; r += NWARP)
        out[(size_t)r * N_DIM + col0 + lane] = sZq[r * NB + lane];
    for (int r = wid; r < 256; r += NWARP)
        out[(size_t)(64 + r) * N_DIM + col0 + lane] = sZm[r * NB + lane];
}

// ---------------------------------------------------------------------------
// Launch
// ---------------------------------------------------------------------------
extern "C" void kernel_launch(void* const* d_in, const int* in_sizes, int n_in,
                              void* d_out, int out_size)
{
    const float* X = (const float*)d_in[0];
    const float* D = (const float*)d_in[1];
    // Defensive: identify by size (X has 256*65536 elems, D has 256*64)
    if (n_in >= 2 && in_sizes[0] == M_DIM * Q_DIM) {
        X = (const float*)d_in[1];
        D = (const float*)d_in[0];
    }
    float* out = (float*)d_out;

    const size_t prep_smem = (size_t)(256 * 64 + 64 * 64 + 64 + 64 + 2) * sizeof(float);
    const size_t main_smem = (size_t)(64 * DT_STRIDE + 3 * 64 * NB + 3 * 256 * NB) * sizeof(float);

    cudaFuncSetAttribute(prep_kernel, cudaFuncAttributeMaxDynamicSharedMemorySize,
                         (int)prep_smem);
    cudaFuncSetAttribute(ista_kernel, cudaFuncAttributeMaxDynamicSharedMemorySize,
                         (int)main_smem);

    prep_kernel<<<1, 256, prep_smem>>>(D);
    ista_kernel<<<N_DIM / NB, THREADS, main_smem>>>(X, D, out);
}

// round 8
// speedup vs baseline: 1.0016x; 1.0001x over previous
#include <cuda_runtime.h>
#include <math.h>

// Problem constants
#define M_DIM 256
#define Q_DIM 64
#define N_DIM 65536
#define NB 32            // columns per CTA (== warp size; lane = column)
#define THREADS 512
#define NWARP 16
#define T_ITERS 16
#define PM_ITERS 200
#define LAMBDA_STAR 0.1f
#define LAMBDA_O 0.1f
#define DT_STRIDE 260    // 256 + 4 pad (bank-conflict relief, keeps 16B alignment)

// eta, thr, c_q, c_m
__device__ float g_consts[4];

// ---------------------------------------------------------------------------
// Prep: G = D^T D, power iteration for alpha = lambda_max(G), derive constants.
// Single block, 256 threads.
// ---------------------------------------------------------------------------
__global__ void prep_kernel(const float* __restrict__ D)
{
    extern __shared__ float sm[];
    float* sD   = sm;                 // [256][64]
    float* sG   = sD + 256 * 64;      // [64][64]
    float* sx   = sG + 64 * 64;       // [64]
    float* sy   = sx + 64;            // [64]
    float* sred = sy + 64;            // [2]

    const int t = threadIdx.x;

    for (int i = t; i < 256 * 64; i += blockDim.x) sD[i] = D[i];
    __syncthreads();

    // G = D^T D : each thread computes a 4x4 block (16x16 grid of blocks)
    {
        const int bi = t & 15, bj = t >> 4;
        const int i0 = bi * 4, j0 = bj * 4;
        float acc[4][4];
        #pragma unroll
        for (int a = 0; a < 4; a++)
            #pragma unroll
            for (int b = 0; b < 4; b++) acc[a][b] = 0.f;

        for (int k = 0; k < 256; k++) {
            const float4 av = *(const float4*)&sD[k * 64 + i0];
            const float4 bv = *(const float4*)&sD[k * 64 + j0];
            const float ai[4] = {av.x, av.y, av.z, av.w};
            const float bjv[4] = {bv.x, bv.y, bv.z, bv.w};
            #pragma unroll
            for (int a = 0; a < 4; a++)
                #pragma unroll
                for (int b = 0; b < 4; b++) acc[a][b] += ai[a] * bjv[b];
        }
        #pragma unroll
        for (int a = 0; a < 4; a++)
            #pragma unroll
            for (int b = 0; b < 4; b++) sG[(i0 + a) * 64 + (j0 + b)] = acc[a][b];
    }

    if (t < 64) sx[t] = 1.0f;
    __syncthreads();

    float alpha = 0.f;
    for (int it = 0; it < PM_ITERS; it++) {
        if (t < 64) {
            const float* g = &sG[t * 64];
            float y = 0.f;
            #pragma unroll 8
            for (int j = 0; j < 64; j++) y += g[j] * sx[j];
            sy[t] = y;
        }
        __syncthreads();

        float ss = 0.f;
        if (t < 64) { float y = sy[t]; ss = y * y; }
        #pragma unroll
        for (int off = 16; off > 0; off >>= 1)
            ss += __shfl_down_sync(0xffffffffu, ss, off);
        if (t < 64 && (t & 31) == 0) sred[t >> 5] = ss;
        __syncthreads();

        const float nm = sqrtf(sred[0] + sred[1]);
        if (t < 64) sx[t] = sy[t] / nm;
        alpha = nm;
        __syncthreads();
    }

    if (t == 0) {
        const float eta = 1.0f / alpha;
        g_consts[0] = eta;
        g_consts[1] = LAMBDA_O * eta;                       // threshold (m rows)
        g_consts[2] = 1.0f - eta * LAMBDA_STAR;             // c_q
        g_consts[3] = 1.0f - eta * (1.0f + LAMBDA_STAR);    // c_m
    }
}

// ---------------------------------------------------------------------------
// Main ISTA kernel. One CTA = 32 columns (lane = column), state in SMEM:
//   b = [b_q(64); b_m(256)], Z likewise, per iteration:
//     Znew = relu(b - t); d = Znew - Z; Z = Znew
//     w = D @ d_q                 (256 x 32)
//     b_m += c_m*d_m - eta*w;  s = w + d_m  (stored in place of d_m)
//     y = D^T @ s                 (64 x 32)
//     b_q += c_q*d_q - eta*y
//   (last iteration skips the b-update; it is dead in the reference scan)
// ---------------------------------------------------------------------------
__global__ void __launch_bounds__(THREADS)
ista_kernel(const float* __restrict__ X, const float* __restrict__ D,
            float* __restrict__ out)
{
    extern __shared__ float sm[];
    float* sDT = sm;                        // [64][DT_STRIDE]  D^T (padded)
    float* sbq = sDT + 64 * DT_STRIDE;      // [64][32]
    float* sZq = sbq + 64 * NB;             // [64][32]
    float* sdq = sZq + 64 * NB;             // [64][32]
    float* sbm = sdq + 64 * NB;             // [256][32]
    float* sZm = sbm + 256 * NB;            // [256][32]
    float* sdm = sZm + 256 * NB;            // [256][32]  (dv, then s = w+dv)

    const int tid  = threadIdx.x;
    const int lane = tid & 31;
    const int wid  = tid >> 5;
    const int col0 = blockIdx.x * NB;

    const float eta = g_consts[0];
    const float thr = g_consts[1];
    const float cq  = g_consts[2];
    const float cm  = g_consts[3];

    // Load D transposed: sDT[q][k] = D[k][q]
    for (int k = wid; k < 256; k += NWARP) {
        #pragma unroll
        for (int q = lane; q < 64; q += 32)
            sDT[q * DT_STRIDE + k] = D[k * 64 + q];
    }

    // Load X tile; init b_m = eta*x, Z = 0; stash x in sdm for the b_q GEMV
    for (int r = wid; r < 256; r += NWARP) {
        const float x = X[(size_t)r * N_DIM + col0 + lane];
        const int idx = r * NB + lane;
        sdm[idx] = x;
        sbm[idx] = eta * x;
        sZm[idx] = 0.f;
    }
    for (int r = wid; r < 64; r += NWARP) sZq[r * NB + lane] = 0.f;
    __syncthreads();

    // b_q = eta * D^T x   (4 rows per warp)
    {
        const int r0 = wid * 4;
        float acc[4] = {0.f, 0.f, 0.f, 0.f};
        for (int k = 0; k < 256; k += 4) {
            const float s0 = sdm[(k + 0) * NB + lane];
            const float s1 = sdm[(k + 1) * NB + lane];
            const float s2 = sdm[(k + 2) * NB + lane];
            const float s3 = sdm[(k + 3) * NB + lane];
            #pragma unroll
            for (int j = 0; j < 4; j++) {
                const float4 d = *(const float4*)&sDT[(r0 + j) * DT_STRIDE + k];
                acc[j] += d.x * s0 + d.y * s1 + d.z * s2 + d.w * s3;
            }
        }
        #pragma unroll
        for (int j = 0; j < 4; j++) sbq[(r0 + j) * NB + lane] = eta * acc[j];
    }
    __syncthreads();

    for (int it = 0; it < T_ITERS; it++) {
        // ---- phase 1: threshold + delta --------------------------------
        #pragma unroll
        for (int r = wid; r < 64; r += NWARP) {
            const int idx = r * NB + lane;
            const float zn = fmaxf(0.f, sbq[idx]);
            sdq[idx] = zn - sZq[idx];
            sZq[idx] = zn;
        }
        #pragma unroll
        for (int r = wid; r < 256; r += NWARP) {
            const int idx = r * NB + lane;
            const float zn = fmaxf(0.f, sbm[idx] - thr);
            sdm[idx] = zn - sZm[idx];
            sZm[idx] = zn;
        }
        __syncthreads();

        if (it == T_ITERS - 1) break;   // final b-update is dead

        // ---- phase A: w = D @ dq ; b_m update ; s = w + dv in place ----
        {
            const int r0 = wid * 16;
            float acc[16];
            #pragma unroll
            for (int j = 0; j < 16; j++) acc[j] = 0.f;

            #pragma unroll 4
            for (int k = 0; k < 64; k++) {
                const float dval = sdq[k * NB + lane];
                const float4* dp = (const float4*)&sDT[k * DT_STRIDE + r0];
                const float4 a0 = dp[0], a1 = dp[1], a2 = dp[2], a3 = dp[3];
                acc[0]  += a0.x * dval; acc[1]  += a0.y * dval;
                acc[2]  += a0.z * dval; acc[3]  += a0.w * dval;
                acc[4]  += a1.x * dval; acc[5]  += a1.y * dval;
                acc[6]  += a1.z * dval; acc[7]  += a1.w * dval;
                acc[8]  += a2.x * dval; acc[9]  += a2.y * dval;
                acc[10] += a2.z * dval; acc[11] += a2.w * dval;
                acc[12] += a3.x * dval; acc[13] += a3.y * dval;
                acc[14] += a3.z * dval; acc[15] += a3.w * dval;
            }
            #pragma unroll
            for (int j = 0; j < 16; j++) {
                const int idx = (r0 + j) * NB + lane;
                const float dvv = sdm[idx];
                const float w = acc[j];
                sbm[idx] += cm * dvv - eta * w;
                sdm[idx] = w + dvv;            // s = D*du + dv
            }
        }
        __syncthreads();

        // ---- phase B: y = D^T @ s ; b_q update -------------------------
        {
            const int r0 = wid * 4;
            float acc[4] = {0.f, 0.f, 0.f, 0.f};
            #pragma unroll 2
            for (int k = 0; k < 256; k += 4) {
                const float s0 = sdm[(k + 0) * NB + lane];
                const float s1 = sdm[(k + 1) * NB + lane];
                const float s2 = sdm[(k + 2) * NB + lane];
                const float s3 = sdm[(k + 3) * NB + lane];
                #pragma unroll
                for (int j = 0; j < 4; j++) {
                    const float4 d = *(const float4*)&sDT[(r0 + j) * DT_STRIDE + k];
                    acc[j] += d.x * s0 + d.y * s1 + d.z * s2 + d.w * s3;
                }
            }
            #pragma unroll
            for (int j = 0; j < 4; j++) {
                const int idx = (r0 + j) * NB + lane;
                sbq[idx] += cq * sdq[idx] - eta * acc[j];
            }
        }
        __syncthreads();
    }

    // ---- output: Z = [Z_q ; Z_m], row-major [320, 65536] ----------------
    for (int r = wid; r < 64; r += NWARP)
        out[(size_t)r * N_DIM + col0 + lane] = sZq[r * NB + lane];
    for (int r = wid; r < 256; r += NWARP)
        out[(size_t)(64 + r) * N_DIM + col0 + lane] = sZm[r * NB + lane];
}

// ---------------------------------------------------------------------------
// Launch
// ---------------------------------------------------------------------------
extern "C" void kernel_launch(void* const* d_in, const int* in_sizes, int n_in,
                              void* d_out, int out_size)
{
    const float* X = (const float*)d_in[0];
    const float* D = (const float*)d_in[1];
    // Defensive: identify by size (X has 256*65536 elems, D has 256*64)
    if (n_in >= 2 && in_sizes[0] == M_DIM * Q_DIM) {
        X = (const float*)d_in[1];
        D = (const float*)d_in[0];
    }
    float* out = (float*)d_out;

    const size_t prep_smem = (size_t)(256 * 64 + 64 * 64 + 64 + 64 + 2) * sizeof(float);
    const size_t main_smem = (size_t)(64 * DT_STRIDE + 3 * 64 * NB + 3 * 256 * NB) * sizeof(float);

    cudaFuncSetAttribute(prep_kernel, cudaFuncAttributeMaxDynamicSharedMemorySize,
                         (int)prep_smem);
    cudaFuncSetAttribute(ista_kernel, cudaFuncAttributeMaxDynamicSharedMemorySize,
                         (int)main_smem);

    prep_kernel<<<1, 256, prep_smem>>>(D);
    ista_kernel<<<N_DIM / NB, THREADS, main_smem>>>(X, D, out);
}